// round 11
// baseline (speedup 1.0000x reference)
#include <cuda_runtime.h>

#define NH_TOTAL (1024 * 8)
#define TILE_ELEMS 4096
#define SMALL_ELEMS ((size_t)NH_TOTAL * 64)
#define BIG_ELEMS   ((size_t)NH_TOTAL * TILE_ELEMS)

static __device__ __forceinline__ float fmap(float x) {
    return x > 0.0f ? x + 1.0f : __expf(x);
}

__global__ __launch_bounds__(256, 3)
void fr_adamax_kernel(
    const float* __restrict__ q,
    const float* __restrict__ k,
    const float* __restrict__ val,
    const float* __restrict__ Siprev,
    const float* __restrict__ Zi,
    const float* __restrict__ Pi,
    const float* __restrict__ Mi,
    const float* __restrict__ Uiprev,
    const float* __restrict__ Siprev2,
    float* __restrict__ outV,
    float* __restrict__ outSi,
    float* __restrict__ outZ,
    float* __restrict__ outP,
    float* __restrict__ outM,
    float* __restrict__ outU,
    float* __restrict__ outSp)
{
    __shared__ float sMi[TILE_ELEMS];   // cp.async staging for Mi (consumed last)
    __shared__ float sQ[64], sK[64], sVal[64];
    __shared__ float sVp[16][65];
    __shared__ float sVred[128];
    __shared__ float sRed[24];
    __shared__ float sMu, sZ;

    const int b = blockIdx.x;
    const int t = threadIdx.x;
    const size_t sb = (size_t)b * 64;
    const size_t bb = (size_t)b * TILE_ELEMS;

    // ---- Front-batch 16 big LDG.128 per thread (4 register-resident streams) ----
    const float4* Sp4  = (const float4*)(Siprev  + bb);
    const float4* Sp24 = (const float4*)(Siprev2 + bb);
    const float4* Up4  = (const float4*)(Uiprev  + bb);
    const float4* Pi4  = (const float4*)(Pi      + bb);

    float4 sv[4], s2v[4], upv[4], pv[4];
#pragma unroll
    for (int i = 0; i < 4; i++) {
        const int f = t + 256 * i;
        sv[i]  = __ldcs(Sp4  + f);
        s2v[i] = __ldcs(Sp24 + f);
        upv[i] = __ldcs(Up4  + f);
        pv[i]  = __ldcs(Pi4  + f);
    }

    // ---- Mi via cp.async (zero register cost; whole phase 1 to land) ----
    {
        unsigned mA = (unsigned)__cvta_generic_to_shared(sMi);
        const float* gM = Mi + bb;
#pragma unroll
        for (int i = 0; i < 4; i++) {
            const int f = t + 256 * i;
            asm volatile("cp.async.cg.shared.global [%0], [%1], 16;\n"
                         :: "r"(mA + f * 16), "l"(gM + f * 4));
        }
        asm volatile("cp.async.commit_group;\n");
    }

    // ---- Small vectors ----
    float dotv = 0.0f;
    if (t < 64) {
        float Kf = fmap(k[sb + t]);
        float Qf = fmap(q[sb + t]);
        float Zn = Zi[sb + t] + Kf;
        sQ[t] = Qf;
        sK[t] = Kf;
        outZ[sb + t] = Zn;
        dotv = Qf * Zn;
    } else if (t < 128) {
        sVal[t - 64] = val[sb + (t - 64)];
    }
    __syncthreads();

    const int g  = t >> 4;          // d-group 0..15
    const int m0 = (t & 15) << 2;   // m base

    const float vm0 = sVal[m0 + 0];
    const float vm1 = sVal[m0 + 1];
    const float vm2 = sVal[m0 + 2];
    const float vm3 = sVal[m0 + 3];

    float4* oU  = (float4*)(outU  + bb);
    float4* oSp = (float4*)(outSp + bb);

    // ---- Phase 1: norms; stores grouped per array ----
    float sumU = 0.0f, sumS = 0.0f;
#pragma unroll
    for (int i = 0; i < 4; i++) {
        const int f = t + 256 * i;
        const int d = g + 16 * i;
        const float Kd = sK[d];

        float4 u;
        u.x = Kd * vm0; u.y = Kd * vm1; u.z = Kd * vm2; u.w = Kd * vm3;

        float du0 = u.x - upv[i].x, du1 = u.y - upv[i].y;
        float du2 = u.z - upv[i].z, du3 = u.w - upv[i].w;
        sumU += du0 * du0 + du1 * du1 + du2 * du2 + du3 * du3;

        float e0 = sv[i].x - s2v[i].x, e1 = sv[i].y - s2v[i].y;
        float e2 = sv[i].z - s2v[i].z, e3 = sv[i].w - s2v[i].w;
        sumS += e0 * e0 + e1 * e1 + e2 * e2 + e3 * e3;

        __stcs(oU + f, u);
    }
#pragma unroll
    for (int i = 0; i < 4; i++) {
        const int f = t + 256 * i;
        __stcs(oSp + f, sv[i]);
    }

    // ---- Deterministic 3-way block reduce (sumU, sumS, dot) ----
#pragma unroll
    for (int o = 16; o > 0; o >>= 1) {
        sumU += __shfl_down_sync(0xffffffffu, sumU, o);
        sumS += __shfl_down_sync(0xffffffffu, sumS, o);
        dotv += __shfl_down_sync(0xffffffffu, dotv, o);
    }
    if ((t & 31) == 0) {
        const int w = t >> 5;
        sRed[w]      = sumU;
        sRed[8 + w]  = sumS;
        sRed[16 + w] = dotv;
    }
    __syncthreads();

    if (t == 0) {
        float aU = 0.0f, aS = 0.0f, aD = 0.0f;
#pragma unroll
        for (int i = 0; i < 8; i++) {
            aU += sRed[i]; aS += sRed[8 + i]; aD += sRed[16 + i];
        }
        float r  = 1.0f - sqrtf(0.5f * sqrtf(aU) / sqrtf(aS));   // STEPSIZE=0.5
        float mu = r * r;
        sMu = fminf(fmaxf(mu, 0.0f), 1.0f - 0.001f);              // clip [0,1-DELTA]
        sZ  = 1.0f / (aD + 1e-6f);                                // EPS
    }
    asm volatile("cp.async.wait_group 0;\n");
    __syncthreads();

    const float mu = sMu;

    // ---- Phase 2: Pi/Siprev register-resident, Mi from shared ----
    float4* oS = (float4*)(outSi + bb);
    float4* oP = (float4*)(outP  + bb);
    float4* oM = (float4*)(outM  + bb);

    float v0 = 0.0f, v1 = 0.0f, v2 = 0.0f, v3 = 0.0f;

#pragma unroll
    for (int i = 0; i < 4; i++) {
        const int f = t + 256 * i;
        const int d = g + 16 * i;
        const float Kd = sK[d];
        const float Qd = sQ[d];

        float4 mi = *(const float4*)&sMi[4 * f];

        float u0 = Kd * vm0, u1 = Kd * vm1, u2 = Kd * vm2, u3 = Kd * vm3;

        float4 pn;
        pn.x = mu * pv[i].x - 0.5f * u0;
        pn.y = mu * pv[i].y - 0.5f * u1;
        pn.z = mu * pv[i].z - 0.5f * u2;
        pn.w = mu * pv[i].w - 0.5f * u3;

        float4 mn;
        mn.x = fmaxf(0.9f * mi.x, fabsf(u0));
        mn.y = fmaxf(0.9f * mi.y, fabsf(u1));
        mn.z = fmaxf(0.9f * mi.z, fabsf(u2));
        mn.w = fmaxf(0.9f * mi.w, fabsf(u3));

        float4 s = sv[i];
        float4 si;
        si.x = s.x - pn.x * rsqrtf(mn.x + 1e-16f);
        si.y = s.y - pn.y * rsqrtf(mn.y + 1e-16f);
        si.z = s.z - pn.z * rsqrtf(mn.z + 1e-16f);
        si.w = s.w - pn.w * rsqrtf(mn.w + 1e-16f);

        __stcs(oP + f, pn);
        __stcs(oM + f, mn);
        __stcs(oS + f, si);

        v0 += Qd * si.x;
        v1 += Qd * si.y;
        v2 += Qd * si.z;
        v3 += Qd * si.w;
    }

    // ---- Deterministic V reduction: 128 half-sums, 64 finish ----
    sVp[g][m0 + 0] = v0;
    sVp[g][m0 + 1] = v1;
    sVp[g][m0 + 2] = v2;
    sVp[g][m0 + 3] = v3;
    __syncthreads();

    if (t < 128) {
        const int m = t & 63;
        const int h = t >> 6;           // 0: groups 0-7, 1: groups 8-15
        float acc = 0.0f;
#pragma unroll
        for (int gg = 0; gg < 8; gg++) acc += sVp[h * 8 + gg][m];
        sVred[h * 64 + m] = acc;
    }
    __syncthreads();
    if (t < 64) {
        outV[sb + t] = (sVred[t] + sVred[64 + t]) * sZ;
    }
}

extern "C" void kernel_launch(void* const* d_in, const int* in_sizes, int n_in,
                              void* d_out, int out_size) {
    const float* q    = (const float*)d_in[0];
    const float* k    = (const float*)d_in[1];
    const float* val  = (const float*)d_in[2];
    const float* Sip  = (const float*)d_in[3];
    const float* Zi   = (const float*)d_in[4];
    const float* Pi   = (const float*)d_in[5];
    const float* Mi   = (const float*)d_in[6];
    const float* Uip  = (const float*)d_in[7];
    const float* Sip2 = (const float*)d_in[8];

    float* out = (float*)d_out;
    float* outV  = out;
    float* outSi = outV  + SMALL_ELEMS;
    float* outZ  = outSi + BIG_ELEMS;
    float* outP  = outZ  + SMALL_ELEMS;
    float* outM  = outP  + BIG_ELEMS;
    float* outU  = outM  + BIG_ELEMS;
    float* outSp = outU  + BIG_ELEMS;

    fr_adamax_kernel<<<NH_TOTAL, 256>>>(
        q, k, val, Sip, Zi, Pi, Mi, Uip, Sip2,
        outV, outSi, outZ, outP, outM, outU, outSp);
}

// round 13
// speedup vs baseline: 1.0058x; 1.0058x over previous
#include <cuda_runtime.h>

#define NH_TOTAL (1024 * 8)
#define TILE_ELEMS 4096
#define SMALL_ELEMS ((size_t)NH_TOTAL * 64)
#define BIG_ELEMS   ((size_t)NH_TOTAL * TILE_ELEMS)

static __device__ __forceinline__ float fmap(float x) {
    return x > 0.0f ? x + 1.0f : __expf(x);
}

__global__ __launch_bounds__(256, 2)
void fr_adamax_kernel(
    const float* __restrict__ q,
    const float* __restrict__ k,
    const float* __restrict__ val,
    const float* __restrict__ Siprev,
    const float* __restrict__ Zi,
    const float* __restrict__ Pi,
    const float* __restrict__ Mi,
    const float* __restrict__ Uiprev,
    const float* __restrict__ Siprev2,
    float* __restrict__ outV,
    float* __restrict__ outSi,
    float* __restrict__ outZ,
    float* __restrict__ outP,
    float* __restrict__ outM,
    float* __restrict__ outU,
    float* __restrict__ outSp)
{
    __shared__ float sQ[64], sK[64], sVal[64];
    __shared__ float sVp[16][65];
    __shared__ float sVred[128];
    __shared__ float sRed[24];

    const int b = blockIdx.x;
    const int t = threadIdx.x;
    const size_t sb = (size_t)b * 64;
    const size_t bb = (size_t)b * TILE_ELEMS;

    // ---- Front-batch ALL 20 big LDG.128 per thread (max MLP at issue) ----
    const float4* Sp4  = (const float4*)(Siprev  + bb);
    const float4* Sp24 = (const float4*)(Siprev2 + bb);
    const float4* Up4  = (const float4*)(Uiprev  + bb);
    const float4* Pi4  = (const float4*)(Pi      + bb);
    const float4* Mi4  = (const float4*)(Mi      + bb);

    float4 sv[4], s2v[4], upv[4], pv[4], miv[4];
#pragma unroll
    for (int i = 0; i < 4; i++) {
        const int f = t + 256 * i;
        sv[i]  = __ldcs(Sp4  + f);
        s2v[i] = __ldcs(Sp24 + f);
        upv[i] = __ldcs(Up4  + f);
    }
#pragma unroll
    for (int i = 0; i < 4; i++) {
        const int f = t + 256 * i;
        pv[i]  = __ldcs(Pi4 + f);
        miv[i] = __ldcs(Mi4 + f);
    }

    // ---- Small vectors (issued after the big batch; consumed at barrier) ----
    float dotv = 0.0f;
    if (t < 64) {
        float Kf = fmap(k[sb + t]);
        float Qf = fmap(q[sb + t]);
        float Zn = Zi[sb + t] + Kf;
        sQ[t] = Qf;
        sK[t] = Kf;
        outZ[sb + t] = Zn;
        dotv = Qf * Zn;
    } else if (t < 128) {
        sVal[t - 64] = val[sb + (t - 64)];
    }
    __syncthreads();

    const int g  = t >> 4;          // d-group 0..15
    const int m0 = (t & 15) << 2;   // m base

    const float vm0 = sVal[m0 + 0];
    const float vm1 = sVal[m0 + 1];
    const float vm2 = sVal[m0 + 2];
    const float vm3 = sVal[m0 + 3];

    float4* oU  = (float4*)(outU  + bb);
    float4* oSp = (float4*)(outSp + bb);

    // ---- Phase 1: norms + mu-independent outputs (outU, outSp) ----
    float sumU = 0.0f, sumS = 0.0f;
#pragma unroll
    for (int i = 0; i < 4; i++) {
        const int f = t + 256 * i;
        const int d = g + 16 * i;
        const float Kd = sK[d];

        float4 u;
        u.x = Kd * vm0; u.y = Kd * vm1; u.z = Kd * vm2; u.w = Kd * vm3;

        float du0 = u.x - upv[i].x, du1 = u.y - upv[i].y;
        float du2 = u.z - upv[i].z, du3 = u.w - upv[i].w;
        sumU += du0 * du0 + du1 * du1 + du2 * du2 + du3 * du3;

        float e0 = sv[i].x - s2v[i].x, e1 = sv[i].y - s2v[i].y;
        float e2 = sv[i].z - s2v[i].z, e3 = sv[i].w - s2v[i].w;
        sumS += e0 * e0 + e1 * e1 + e2 * e2 + e3 * e3;

        __stcs(oU  + f, u);
        __stcs(oSp + f, sv[i]);
    }

    // ---- Deterministic 3-way block reduce (single barrier) ----
#pragma unroll
    for (int o = 16; o > 0; o >>= 1) {
        sumU += __shfl_down_sync(0xffffffffu, sumU, o);
        sumS += __shfl_down_sync(0xffffffffu, sumS, o);
        dotv += __shfl_down_sync(0xffffffffu, dotv, o);
    }
    if ((t & 31) == 0) {
        const int w = t >> 5;
        sRed[w]      = sumU;
        sRed[8 + w]  = sumS;
        sRed[16 + w] = dotv;
    }
    __syncthreads();

    // ---- Redundant per-thread finalization (no second barrier, no t0 serial) ----
    float mu;
    {
        float aU = 0.0f, aS = 0.0f;
#pragma unroll
        for (int i = 0; i < 8; i++) { aU += sRed[i]; aS += sRed[8 + i]; }
        float r = 1.0f - sqrtf(0.5f * sqrtf(aU) / sqrtf(aS));   // STEPSIZE=0.5
        mu = r * r;
        mu = fminf(fmaxf(mu, 0.0f), 1.0f - 0.001f);             // clip [0,1-DELTA]
    }

    // ---- Phase 2: all register-resident; emit Si/Pn/Mn; fold V ----
    float4* oS = (float4*)(outSi + bb);
    float4* oP = (float4*)(outP  + bb);
    float4* oM = (float4*)(outM  + bb);

    float v0 = 0.0f, v1 = 0.0f, v2 = 0.0f, v3 = 0.0f;

#pragma unroll
    for (int i = 0; i < 4; i++) {
        const int f = t + 256 * i;
        const int d = g + 16 * i;
        const float Kd = sK[d];
        const float Qd = sQ[d];

        float u0 = Kd * vm0, u1 = Kd * vm1, u2 = Kd * vm2, u3 = Kd * vm3;

        float4 pn;
        pn.x = mu * pv[i].x - 0.5f * u0;
        pn.y = mu * pv[i].y - 0.5f * u1;
        pn.z = mu * pv[i].z - 0.5f * u2;
        pn.w = mu * pv[i].w - 0.5f * u3;

        float4 mn;
        mn.x = fmaxf(0.9f * miv[i].x, fabsf(u0));
        mn.y = fmaxf(0.9f * miv[i].y, fabsf(u1));
        mn.z = fmaxf(0.9f * miv[i].z, fabsf(u2));
        mn.w = fmaxf(0.9f * miv[i].w, fabsf(u3));

        float4 s = sv[i];
        float4 si;
        si.x = s.x - pn.x * rsqrtf(mn.x + 1e-16f);
        si.y = s.y - pn.y * rsqrtf(mn.y + 1e-16f);
        si.z = s.z - pn.z * rsqrtf(mn.z + 1e-16f);
        si.w = s.w - pn.w * rsqrtf(mn.w + 1e-16f);

        __stcs(oP + f, pn);
        __stcs(oM + f, mn);
        __stcs(oS + f, si);

        v0 += Qd * si.x;
        v1 += Qd * si.y;
        v2 += Qd * si.z;
        v3 += Qd * si.w;
    }

    // ---- Deterministic V reduction: 128 half-sums into scratch, 64 finish ----
    sVp[g][m0 + 0] = v0;
    sVp[g][m0 + 1] = v1;
    sVp[g][m0 + 2] = v2;
    sVp[g][m0 + 3] = v3;
    __syncthreads();

    if (t < 128) {
        const int m = t & 63;
        const int h = t >> 6;           // 0: groups 0-7, 1: groups 8-15
        float acc = 0.0f;
#pragma unroll
        for (int gg = 0; gg < 8; gg++) acc += sVp[h * 8 + gg][m];
        sVred[h * 64 + m] = acc;
    }
    __syncthreads();
    if (t < 64) {
        float aD = 0.0f;
#pragma unroll
        for (int i = 0; i < 8; i++) aD += sRed[16 + i];
        outV[sb + t] = (sVred[t] + sVred[64 + t]) / (aD + 1e-6f);  // EPS
    }
}

extern "C" void kernel_launch(void* const* d_in, const int* in_sizes, int n_in,
                              void* d_out, int out_size) {
    const float* q    = (const float*)d_in[0];
    const float* k    = (const float*)d_in[1];
    const float* val  = (const float*)d_in[2];
    const float* Sip  = (const float*)d_in[3];
    const float* Zi   = (const float*)d_in[4];
    const float* Pi   = (const float*)d_in[5];
    const float* Mi   = (const float*)d_in[6];
    const float* Uip  = (const float*)d_in[7];
    const float* Sip2 = (const float*)d_in[8];

    float* out = (float*)d_out;
    float* outV  = out;
    float* outSi = outV  + SMALL_ELEMS;
    float* outZ  = outSi + BIG_ELEMS;
    float* outP  = outZ  + SMALL_ELEMS;
    float* outM  = outP  + BIG_ELEMS;
    float* outU  = outM  + BIG_ELEMS;
    float* outSp = outU  + BIG_ELEMS;

    fr_adamax_kernel<<<NH_TOTAL, 256>>>(
        q, k, val, Sip, Zi, Pi, Mi, Uip, Sip2,
        outV, outSi, outZ, outP, outM, outU, outSp);
}

// round 14
// speedup vs baseline: 1.0102x; 1.0044x over previous
#include <cuda_runtime.h>

#define NH_TOTAL (1024 * 8)
#define TILE_ELEMS 4096
#define SMALL_ELEMS ((size_t)NH_TOTAL * 64)
#define BIG_ELEMS   ((size_t)NH_TOTAL * TILE_ELEMS)

static __device__ __forceinline__ float fmap(float x) {
    return x > 0.0f ? x + 1.0f : __expf(x);
}

// 256-bit global load/store (sm_100+), streaming (evict-first) policy
#define LDG256_CS(r, p)                                                       \
    asm("ld.global.cs.v8.f32 {%0,%1,%2,%3,%4,%5,%6,%7}, [%8];"                \
        : "=f"((r)[0]), "=f"((r)[1]), "=f"((r)[2]), "=f"((r)[3]),             \
          "=f"((r)[4]), "=f"((r)[5]), "=f"((r)[6]), "=f"((r)[7])              \
        : "l"(p))

#define STG256_CS(p, r)                                                       \
    asm volatile("st.global.cs.v8.f32 [%0], {%1,%2,%3,%4,%5,%6,%7,%8};"       \
                 :: "l"(p),                                                   \
                    "f"((r)[0]), "f"((r)[1]), "f"((r)[2]), "f"((r)[3]),       \
                    "f"((r)[4]), "f"((r)[5]), "f"((r)[6]), "f"((r)[7])        \
                 : "memory")

__global__ __launch_bounds__(256, 2)
void fr_adamax_kernel(
    const float* __restrict__ q,
    const float* __restrict__ k,
    const float* __restrict__ val,
    const float* __restrict__ Siprev,
    const float* __restrict__ Zi,
    const float* __restrict__ Pi,
    const float* __restrict__ Mi,
    const float* __restrict__ Uiprev,
    const float* __restrict__ Siprev2,
    float* __restrict__ outV,
    float* __restrict__ outSi,
    float* __restrict__ outZ,
    float* __restrict__ outP,
    float* __restrict__ outM,
    float* __restrict__ outU,
    float* __restrict__ outSp)
{
    __shared__ float sQ[64], sK[64], sVal[64];
    __shared__ float sVp[32][65];
    __shared__ float sVred[128];
    __shared__ float sRed[24];
    __shared__ float sMu, sZ;

    const int b = blockIdx.x;
    const int t = threadIdx.x;
    const size_t sb = (size_t)b * 64;
    const size_t bb = (size_t)b * TILE_ELEMS;

    // Thread mapping: chunk c = t + 256*i (i=0,1), elements [8c, 8c+8)
    //   d = c/8 = t/8 + 32*i,  m0 = 8*(t&7)
    const int g  = t >> 3;          // d for i=0 (0..31); d for i=1 is g+32
    const int m0 = (t & 7) << 3;    // m base (8 consecutive)

    // ---- Front-batch ALL 10 LDG.256 per thread (max MLP at issue) ----
    float sv[2][8], s2v[2][8], upv[2][8], pv[2][8], miv[2][8];
#pragma unroll
    for (int i = 0; i < 2; i++) {
        const size_t off = bb + (size_t)(t + 256 * i) * 8;
        LDG256_CS(sv[i],  Siprev  + off);
        LDG256_CS(s2v[i], Siprev2 + off);
        LDG256_CS(upv[i], Uiprev  + off);
        LDG256_CS(pv[i],  Pi      + off);
        LDG256_CS(miv[i], Mi      + off);
    }

    // ---- Small vectors (issued after the big batch; consumed at barrier) ----
    float dotv = 0.0f;
    if (t < 64) {
        float Kf = fmap(k[sb + t]);
        float Qf = fmap(q[sb + t]);
        float Zn = Zi[sb + t] + Kf;
        sQ[t] = Qf;
        sK[t] = Kf;
        outZ[sb + t] = Zn;
        dotv = Qf * Zn;
    } else if (t < 128) {
        sVal[t - 64] = val[sb + (t - 64)];
    }
    __syncthreads();

    float vm[8];
#pragma unroll
    for (int j = 0; j < 8; j++) vm[j] = sVal[m0 + j];

    // ---- Phase 1: norms + mu-independent outputs (outU, outSp) ----
    float sumU = 0.0f, sumS = 0.0f;
#pragma unroll
    for (int i = 0; i < 2; i++) {
        const size_t off = bb + (size_t)(t + 256 * i) * 8;
        const float Kd = sK[g + 32 * i];

        float u[8];
#pragma unroll
        for (int j = 0; j < 8; j++) {
            u[j] = Kd * vm[j];
            float du = u[j] - upv[i][j];
            sumU += du * du;
            float e = sv[i][j] - s2v[i][j];
            sumS += e * e;
        }
        STG256_CS(outU  + off, u);
        STG256_CS(outSp + off, sv[i]);
    }

    // ---- Deterministic 3-way block reduce (sumU, sumS, dot) ----
#pragma unroll
    for (int o = 16; o > 0; o >>= 1) {
        sumU += __shfl_down_sync(0xffffffffu, sumU, o);
        sumS += __shfl_down_sync(0xffffffffu, sumS, o);
        dotv += __shfl_down_sync(0xffffffffu, dotv, o);
    }
    if ((t & 31) == 0) {
        const int w = t >> 5;
        sRed[w]      = sumU;
        sRed[8 + w]  = sumS;
        sRed[16 + w] = dotv;
    }
    __syncthreads();

    if (t == 0) {
        float aU = 0.0f, aS = 0.0f, aD = 0.0f;
#pragma unroll
        for (int i = 0; i < 8; i++) {
            aU += sRed[i]; aS += sRed[8 + i]; aD += sRed[16 + i];
        }
        float r  = 1.0f - sqrtf(0.5f * sqrtf(aU) / sqrtf(aS));   // STEPSIZE=0.5
        float mu = r * r;
        sMu = fminf(fmaxf(mu, 0.0f), 1.0f - 0.001f);              // clip [0,1-DELTA]
        sZ  = 1.0f / (aD + 1e-6f);                                // EPS
    }
    __syncthreads();

    const float mu = sMu;

    // ---- Phase 2: all register-resident; emit Si/Pn/Mn; fold V ----
    float v[8];
#pragma unroll
    for (int j = 0; j < 8; j++) v[j] = 0.0f;

#pragma unroll
    for (int i = 0; i < 2; i++) {
        const size_t off = bb + (size_t)(t + 256 * i) * 8;
        const int d = g + 32 * i;
        const float Kd = sK[d];
        const float Qd = sQ[d];

        float pn[8], mn[8], si[8];
#pragma unroll
        for (int j = 0; j < 8; j++) {
            float u = Kd * vm[j];
            pn[j] = mu * pv[i][j] - 0.5f * u;
            mn[j] = fmaxf(0.9f * miv[i][j], fabsf(u));
            si[j] = sv[i][j] - pn[j] * rsqrtf(mn[j] + 1e-16f);
            v[j] += Qd * si[j];
        }
        STG256_CS(outP  + off, pn);
        STG256_CS(outM  + off, mn);
        STG256_CS(outSi + off, si);
    }

    // ---- Deterministic V reduction over the 32 d-groups ----
#pragma unroll
    for (int j = 0; j < 8; j++) sVp[g][m0 + j] = v[j];
    __syncthreads();

    if (t < 128) {
        const int m = t & 63;
        const int h = t >> 6;           // 0: rows 0-15, 1: rows 16-31
        float acc = 0.0f;
#pragma unroll
        for (int gg = 0; gg < 16; gg++) acc += sVp[h * 16 + gg][m];
        sVred[h * 64 + m] = acc;
    }
    __syncthreads();
    if (t < 64) {
        outV[sb + t] = (sVred[t] + sVred[64 + t]) * sZ;
    }
}

extern "C" void kernel_launch(void* const* d_in, const int* in_sizes, int n_in,
                              void* d_out, int out_size) {
    const float* q    = (const float*)d_in[0];
    const float* k    = (const float*)d_in[1];
    const float* val  = (const float*)d_in[2];
    const float* Sip  = (const float*)d_in[3];
    const float* Zi   = (const float*)d_in[4];
    const float* Pi   = (const float*)d_in[5];
    const float* Mi   = (const float*)d_in[6];
    const float* Uip  = (const float*)d_in[7];
    const float* Sip2 = (const float*)d_in[8];

    float* out = (float*)d_out;
    float* outV  = out;
    float* outSi = outV  + SMALL_ELEMS;
    float* outZ  = outSi + BIG_ELEMS;
    float* outP  = outZ  + SMALL_ELEMS;
    float* outM  = outP  + BIG_ELEMS;
    float* outU  = outM  + BIG_ELEMS;
    float* outSp = outU  + BIG_ELEMS;

    fr_adamax_kernel<<<NH_TOTAL, 256>>>(
        q, k, val, Sip, Zi, Pi, Mi, Uip, Sip2,
        outV, outSi, outZ, outP, outM, outU, outSp);
}